// round 14
// baseline (speedup 1.0000x reference)
#include <cuda_runtime.h>
#include <math.h>

#define Bn 8
#define Hn 256
#define Wn 256
#define R  3
#define TRB 16                    // output rows per block
#define NROWS (TRB + 2*R)         // 22 halo rows (fits uint32 mask)
#define GW (Wn + 2*R)             // 262 padded columns (idx = col + R)
#define NBLK (Bn * (Hn / TRB))    // 128 blocks
#define PADV 0x0FFF0FFFu          // "far" in both packed halves

// Grid-wide accumulator + completion counter. Both statically zero and reset
// by the last block each launch, so graph replays start clean.
__device__ float g_sum = 0.0f;
__device__ unsigned int g_done = 0;

__device__ __forceinline__ int vdist(unsigned int m, int p)
{
    const unsigned int down = m >> p;
    const unsigned int up   = m << (31 - p);
    const int dd = down ? (__ffs((int)down) - 1) : 63;
    const int du = up   ? __clz((int)up)         : 63;
    return min(dd, du);
}

__global__ void __launch_bounds__(256)
boundary_loss_kernel(const float* __restrict__ pred,
                     const float* __restrict__ targ,
                     float* __restrict__ out)
{
    const int tile = blockIdx.x;             // 0 .. 127
    const int b    = tile >> 4;              // 16 row-tiles per image
    const int h0   = (tile & 15) * TRB;      // first output row of this tile
    const int w    = threadIdx.x;            // column (one per thread)

    __shared__ unsigned int sh[TRB][GW];     // packed (d2_to_bg | d2_to_fg<<16)
    __shared__ float lutW[34];
    __shared__ float ws[8];

    const int base = b * (Hn * Wn);
    const float*        pimg = pred + base;
    const unsigned int* timg = (const unsigned int*)(targ + base);

    // ---- front-batch ALL global loads (38 outstanding) ----
    float xr[TRB];
    #pragma unroll
    for (int r = 0; r < TRB; ++r)
        xr[r] = __ldg(&pimg[(h0 + r) * Wn + w]);

    const int start = h0 - R;
    unsigned int tw[NROWS];
    #pragma unroll
    for (int k = 0; k < NROWS; ++k) {
        const int hh = min(max(start + k, 0), Hn - 1);
        tw[k] = __ldg(&timg[hh * Wn + w]);
    }

    // ---- LUT + pads while loads are in flight ----
    if (w < 34) {
        const float d = (w == 33) ? 64.0f : sqrtf((float)w);
        lutW[w] = __frcp_rn(1.0f + __expf((d - 3.0f) * 0.2f));
    }
    if (w < 6 * TRB) {                       // 96 pad writes: 6 per row
        const int r = w / 6, i = w % 6;
        const int idx = (i < R) ? i : (Wn + i);   // 0..2 / 259..261
        sh[r][idx] = PADV;
    }

    // ---- validity mask + class bitmask (bit 23 of 0.0f/1.0f IS the class) --
    unsigned int vm = (1u << NROWS) - 1u;
    if (start < 0)          vm &= ~((1u << (-start)) - 1u);
    if (start + NROWS > Hn) vm &=  (1u << (Hn - start)) - 1u;

    unsigned int fgm = 0u;
    #pragma unroll
    for (int k = 0; k < NROWS; ++k)
        fgm |= ((tw[k] >> 23) & 1u) << k;
    fgm &= vm;
    const unsigned int bgm = ~fgm & vm;

    // ---- vertical pass: packed d2 for both classes, 16 rows ----
    #pragma unroll
    for (int r = 0; r < TRB; ++r) {
        const int p  = r + R;
        const int dp = vdist(bgm, p);
        const int dn = vdist(fgm, p);
        sh[r][w + R] = (unsigned)(dp * dp) | ((unsigned)(dn * dn) << 16);
    }
    __syncthreads();

    // ---- horizontal 7-tap packed envelope + fused BCE * LUT weight ----
    float acc = 0.0f;
    #pragma unroll
    for (int r = 0; r < TRB; ++r) {
        unsigned int best = 0xFFFFFFFFu;
        #pragma unroll
        for (int k = 0; k < 7; ++k) {
            const int kk = k - R;
            const unsigned int add = (unsigned)(kk * kk) * 0x00010001u;
            best = __vminu2(best, sh[r][w + k] + add);
        }

        const bool fg = (fgm >> (r + R)) & 1u;
        const unsigned int d2 = fg ? (best & 0xFFFFu) : (best >> 16);
        const float weight = lutW[min(d2, 33u)];

        const float x   = xr[r];
        const float bce = fmaxf(x, 0.0f) - (fg ? x : 0.0f)
                        + __logf(1.0f + __expf(-fabsf(x)));
        acc = fmaf(bce, weight, acc);
    }

    // ---- block reduction (8 warps) ----
    #pragma unroll
    for (int off = 16; off > 0; off >>= 1)
        acc += __shfl_xor_sync(0xffffffffu, acc, off);
    if ((w & 31) == 0) ws[w >> 5] = acc;
    __syncthreads();

    // ---- minimal tail: one RED.F32 per block; last block finalizes alone --
    if (w == 0) {
        float s = 0.0f;
        #pragma unroll
        for (int i = 0; i < 8; ++i) s += ws[i];
        atomicAdd(&g_sum, s);
        __threadfence();
        const unsigned int done = atomicAdd(&g_done, 1u);
        if (done == (unsigned int)(NBLK - 1)) {
            __threadfence();                         // acquire all g_sum adds
            const float tot = *(volatile float*)&g_sum;
            out[0] = tot * (1.0f / (float)(Bn * Hn * Wn));
            g_sum  = 0.0f;                           // reset for next replay
            g_done = 0u;
        }
    }
}

extern "C" void kernel_launch(void* const* d_in, const int* in_sizes, int n_in,
                              void* d_out, int out_size)
{
    const float* pred = (const float*)d_in[0];
    const float* targ = (const float*)d_in[1];
    float* out = (float*)d_out;

    boundary_loss_kernel<<<NBLK, 256>>>(pred, targ, out);
}